// round 7
// baseline (speedup 1.0000x reference)
#include <cuda_runtime.h>

// InducingLocationsSpatialTransform: bilinear affine warp
// X: (N=512, H=64, W=64, C=32) f32, theta: (N, 6) f32 -> out: (N,H,W,C) f32
//
// One warp per 32 consecutive pixels (same image, same grid row).
// Phase 1: lane j computes pixel j's corner offsets + bilinear weights
//          (vectorized: one math pass serves 32 pixels).
// Phase 2: per pixel, broadcast params via shfl; 32 lanes load the 4 corner
//          pixels with scalar LDG.32 -> each load touches exactly ONE 128B
//          line (1.0 cyc/wf drain, no within-LDG replays), blend, store.

#define N_ 512
#define H_ 64
#define W_ 64
#define C_ 32
#define HW_ (H_ * W_)

__global__ __launch_bounds__(256, 6) void st_kernel(
    const float* __restrict__ X,
    const float* __restrict__ theta,
    float* __restrict__ out)
{
    const unsigned FULL = 0xffffffffu;
    int lane  = threadIdx.x & 31;
    int wid   = threadIdx.x >> 5;
    int gwarp = blockIdx.x * 8 + wid;
    int wbase = gwarp << 5;            // first pixel of this warp's batch

    int n  = wbase >> 12;              // image index (same for all 32 pixels)
    int p0 = wbase & 4095;
    int y  = p0 >> 6;                  // grid row (same for all 32 pixels)
    int x  = (p0 & 63) + lane;         // lane's pixel column

    const float* th = theta + n * 6;
    float t0 = __ldg(th + 0), t1 = __ldg(th + 1), t2 = __ldg(th + 2);
    float t3 = __ldg(th + 3), t4 = __ldg(th + 4), t5 = __ldg(th + 5);

    // ---- Phase 1: per-lane pixel math (pixel wbase+lane) ----
    const float step = 2.0f / 63.0f;
    float xt = -1.0f + (float)x * step;
    float yt = -1.0f + (float)y * step;

    float gx = (float)W_ * ((t0 * xt + t1 * yt + t2) + 1.0f) * 0.5f;
    float gy = (float)H_ * ((t3 * xt + t4 * yt + t5) + 1.0f) * 0.5f;

    float fx = floorf(gx), fy = floorf(gy);
    int x0 = min(max((int)fx,     0), W_ - 1);
    int x1 = min(max((int)fx + 1, 0), W_ - 1);
    int y0 = min(max((int)fy,     0), H_ - 1);
    int y1 = min(max((int)fy + 1, 0), H_ - 1);

    float wa = ((float)x1 - gx) * ((float)y1 - gy);
    float wb = ((float)x1 - gx) * (gy - (float)y0);
    float wc = (gx - (float)x0) * ((float)y1 - gy);
    float wd = (gx - (float)x0) * (gy - (float)y0);

    int offA = y0 * (W_ * C_) + x0 * C_;          // float offset of corner (y0,x0)
    int code = (x1 - x0) | ((y1 - y0) << 1);      // dx in bit0, dy in bit1

    // ---- Phase 2: gather/blend all 32 pixels, one 128B line per LDG ----
    const float* Sn = X + (size_t)n * (HW_ * C_);
    float*       On = out + (size_t)wbase * C_ + lane;

    #pragma unroll
    for (int j = 0; j < 32; j++) {
        int   off = __shfl_sync(FULL, offA, j);
        int   cd  = __shfl_sync(FULL, code, j);
        float Wa  = __shfl_sync(FULL, wa, j);
        float Wb  = __shfl_sync(FULL, wb, j);
        float Wc  = __shfl_sync(FULL, wc, j);
        float Wd  = __shfl_sync(FULL, wd, j);

        int dx = (cd & 1) << 5;        // 0 or 32 floats  (x0 -> x1)
        int dy = (cd & 2) << 10;       // 0 or 2048 floats (y0 -> y1)

        const float* base = Sn + off + lane;
        float va = __ldg(base);
        float vc = __ldg(base + dx);
        float vb = __ldg(base + dy);
        float vd = __ldg(base + dx + dy);

        On[j * C_] = Wa * va + Wb * vb + Wc * vc + Wd * vd;
    }
}

extern "C" void kernel_launch(void* const* d_in, const int* in_sizes, int n_in,
                              void* d_out, int out_size)
{
    const float* X     = (const float*)d_in[0];
    const float* theta = (const float*)d_in[1];
    float* out         = (float*)d_out;

    // warps total = N*HW/32 = 65536; 8 warps per 256-thread block
    int blocks = (N_ * HW_) / 32 / 8;   // 8192
    st_kernel<<<blocks, 256>>>(X, theta, out);
}

// round 8
// speedup vs baseline: 1.3215x; 1.3215x over previous
#include <cuda_runtime.h>

// InducingLocationsSpatialTransform: bilinear affine warp
// X: (N=512, H=64, W=64, c=32) f32, theta: (N, 6) f32 -> out: (N,H,W,C) f32
//
// One warp per 32 consecutive pixels (same image, same grid row).
// Phase 1: lane j computes pixel j's 4 corner offsets (int4) + weights
//          (float4), staged in smem (one vectorized math pass per 32 px).
// Phase 2: per pixel, two LDS.128 broadcasts fetch params; 32 lanes issue
//          4 scalar LDG.32 gathers -> each load touches exactly ONE 128B
//          line (no within-LDG replays), blend, 1 coalesced STG.

#define N_ 512
#define H_ 64
#define W_ 64
#define C_ 32
#define HW_ (H_ * W_)

__global__ __launch_bounds__(256, 6) void st_kernel(
    const float* __restrict__ X,
    const float* __restrict__ theta,
    float* __restrict__ out)
{
    __shared__ int4   soff[8][32];
    __shared__ float4 swt [8][32];

    int lane  = threadIdx.x & 31;
    int wid   = threadIdx.x >> 5;
    int gwarp = blockIdx.x * 8 + wid;
    int wbase = gwarp << 5;            // first pixel of this warp's batch

    int n  = wbase >> 12;              // image index (same for all 32 pixels)
    int p0 = wbase & 4095;
    int y  = p0 >> 6;                  // grid row (same for all 32 pixels)
    int x  = (p0 & 63) + lane;         // lane's pixel column

    const float* th = theta + n * 6;
    float t0 = __ldg(th + 0), t1 = __ldg(th + 1), t2 = __ldg(th + 2);
    float t3 = __ldg(th + 3), t4 = __ldg(th + 4), t5 = __ldg(th + 5);

    // ---- Phase 1: per-lane pixel math (pixel wbase+lane) ----
    const float step = 2.0f / 63.0f;
    float xt = -1.0f + (float)x * step;
    float yt = -1.0f + (float)y * step;

    float gx = (float)W_ * ((t0 * xt + t1 * yt + t2) + 1.0f) * 0.5f;
    float gy = (float)H_ * ((t3 * xt + t4 * yt + t5) + 1.0f) * 0.5f;

    float fx = floorf(gx), fy = floorf(gy);
    int x0 = min(max((int)fx,     0), W_ - 1);
    int x1 = min(max((int)fx + 1, 0), W_ - 1);
    int y0 = min(max((int)fy,     0), H_ - 1);
    int y1 = min(max((int)fy + 1, 0), H_ - 1);

    float wa = ((float)x1 - gx) * ((float)y1 - gy);
    float wb = ((float)x1 - gx) * (gy - (float)y0);
    float wc = (gx - (float)x0) * ((float)y1 - gy);
    float wd = (gx - (float)x0) * (gy - (float)y0);

    int4 o;
    o.x = y0 * (W_ * C_) + x0 * C_;   // corner (y0,x0)
    o.y = y1 * (W_ * C_) + x0 * C_;   // corner (y1,x0)
    o.z = y0 * (W_ * C_) + x1 * C_;   // corner (y0,x1)
    o.w = y1 * (W_ * C_) + x1 * C_;   // corner (y1,x1)

    soff[wid][lane] = o;
    swt [wid][lane] = make_float4(wa, wb, wc, wd);
    __syncwarp();

    // ---- Phase 2: gather/blend 32 pixels; every LDG hits one 128B line ----
    const float* Sn = X + (size_t)n * (HW_ * C_) + lane;
    float*       On = out + (size_t)wbase * C_ + lane;

    #pragma unroll 4
    for (int j = 0; j < 32; j++) {
        int4   oj = soff[wid][j];     // LDS.128, uniform addr -> broadcast
        float4 wj = swt [wid][j];     // LDS.128 broadcast

        float va = __ldg(Sn + oj.x);
        float vb = __ldg(Sn + oj.y);
        float vc = __ldg(Sn + oj.z);
        float vd = __ldg(Sn + oj.w);

        On[j * C_] = wj.x * va + wj.y * vb + wj.z * vc + wj.w * vd;
    }
}

extern "C" void kernel_launch(void* const* d_in, const int* in_sizes, int n_in,
                              void* d_out, int out_size)
{
    const float* X     = (const float*)d_in[0];
    const float* theta = (const float*)d_in[1];
    float* out         = (float*)d_out;

    // warps total = N*HW/32 = 65536; 8 warps per 256-thread block
    int blocks = (N_ * HW_) / 32 / 8;   // 8192
    st_kernel<<<blocks, 256>>>(X, theta, out);
}